// round 2
// baseline (speedup 1.0000x reference)
#include <cuda_runtime.h>
#include <cstdint>

// Problem constants (from reference)
#define F_FEATS   8
#define BL        (4096 * 20)        // 81920 ids per feature
#define VOCAB     1000000
#define DIM       128                // floats per row
#define N_ROWS    (F_FEATS * BL)     // 655360 output rows

// One warp per output row. Lane l moves float4 l (32 lanes * 16B = 512B row).
// Output feature f sources input feature f^4 (split_sizes=(4,4), order=(1,0)).
__global__ void __launch_bounds__(256, 8)
emb_gather_kernel(const int* __restrict__ values,
                  const float4* __restrict__ table,
                  float4* __restrict__ out)
{
    const int warp_in_block = threadIdx.x >> 5;
    const int lane = threadIdx.x & 31;

    // 8 warps per block; grid-stride over rows for flexibility
    long long row = (long long)blockIdx.x * 8 + warp_in_block;
    const long long row_stride = (long long)gridDim.x * 8;

    for (; row < N_ROWS; row += row_stride) {
        const int f = (int)(row / BL);
        const int i = (int)(row - (long long)f * BL);
        const int src_f = f ^ 4;   // the feature-block permutation

        int id = __ldg(&values[(long long)src_f * BL + i]);
        // slots = vals % VOCAB (ids already in range, but keep exact semantics)
        unsigned slot = (unsigned)id % (unsigned)VOCAB;

        const float4* src = table + (long long)slot * (DIM / 4);
        float4* dst = out + row * (DIM / 4);

        // 32 lanes x float4 = 128 floats = 512 B
        dst[lane] = __ldg(&src[lane]);
    }
}

extern "C" void kernel_launch(void* const* d_in, const int* in_sizes, int n_in,
                              void* d_out, int out_size)
{
    const int*    values = (const int*)d_in[0];
    const float4* table  = (const float4*)d_in[1];
    float4*       out    = (float4*)d_out;

    // 8 warps (rows) per 256-thread block -> exactly cover all rows
    const int blocks = N_ROWS / 8;   // 81920
    emb_gather_kernel<<<blocks, 256>>>(values, table, out);
}

// round 3
// speedup vs baseline: 1.6289x; 1.6289x over previous
#include <cuda_runtime.h>
#include <cstdint>

// Problem constants (from reference)
#define F_FEATS   8
#define BL        81920u             // 4096*20 ids per feature
#define VOCAB     1000000u
#define DIM_V4    32                 // 128 floats = 32 float4 per row
#define N_ROWS    655360u            // F_FEATS * BL output rows
#define ROWS_PER_WARP 4

// Each warp handles 4 consecutive output rows:
//   - 4 uniform id loads (same L1 sector)
//   - 4 back-to-back gather LDG.128 (lane l moves float4 l of each 512B row)
//   - 4 contiguous STG.128 (2KB streaming store)
// Output feature f sources input feature f^4 (split_sizes=(4,4), order=(1,0)).
__global__ void __launch_bounds__(256, 8)
emb_gather_kernel(const int* __restrict__ values,
                  const float4* __restrict__ table,
                  float4* __restrict__ out)
{
    const unsigned lane   = threadIdx.x & 31u;
    const unsigned warpId = blockIdx.x * 8u + (threadIdx.x >> 5);
    const unsigned row0   = warpId * ROWS_PER_WARP;
    if (row0 >= N_ROWS) return;

    // 32-bit const division: f = row0 / 81920 (group never crosses feature edge)
    const unsigned f     = row0 / BL;            // umulhi+shift, cheap
    const unsigned i0    = row0 - f * BL;
    const unsigned src_f = f ^ 4u;               // feature-block permutation

    const int* __restrict__ vptr = values + (size_t)src_f * BL + i0;

    // Phase 1: compute all gather addresses (ids are consecutive -> broadcast loads)
    const float4* src[ROWS_PER_WARP];
    #pragma unroll
    for (int k = 0; k < ROWS_PER_WARP; k++) {
        unsigned slot = (unsigned)__ldg(vptr + k) % VOCAB;
        src[k] = table + (size_t)slot * DIM_V4 + lane;
    }

    // Phase 2: issue all gathers back-to-back (MLP=4 per warp)
    float4 r[ROWS_PER_WARP];
    #pragma unroll
    for (int k = 0; k < ROWS_PER_WARP; k++)
        r[k] = __ldg(src[k]);

    // Phase 3: 2KB contiguous store
    float4* __restrict__ dst = out + (size_t)row0 * DIM_V4 + lane;
    #pragma unroll
    for (int k = 0; k < ROWS_PER_WARP; k++)
        dst[k * DIM_V4] = r[k];
}

extern "C" void kernel_launch(void* const* d_in, const int* in_sizes, int n_in,
                              void* d_out, int out_size)
{
    const int*    values = (const int*)d_in[0];
    const float4* table  = (const float4*)d_in[1];
    float4*       out    = (float4*)d_out;

    // 8 warps/block * 4 rows/warp = 32 rows per block; exact cover
    const int blocks = N_ROWS / (8 * ROWS_PER_WARP);   // 20480
    emb_gather_kernel<<<blocks, 256>>>(values, table, out);
}

// round 4
// speedup vs baseline: 1.6331x; 1.0026x over previous
#include <cuda_runtime.h>
#include <cstdint>

// Problem constants (from reference)
#define F_FEATS   8
#define BL        81920u             // 4096*20 ids per feature
#define VOCAB     1000000u
#define DIM_V4    32                 // 128 floats = 32 float4 per row
#define N_ROWS    655360u            // F_FEATS * BL output rows
#define ROWS_PER_WARP 8

// Each warp handles 8 consecutive output rows:
//   - 8 uniform id loads (two L1 sectors)
//   - 8 back-to-back gather LDG.128 (lane l moves float4 l of each 512B row)
//   - 8 contiguous streaming STG.128 (__stcs: evict-first, keep L2 for table)
// Output feature f sources input feature f^4 (split_sizes=(4,4), order=(1,0)).
__global__ void __launch_bounds__(256, 6)
emb_gather_kernel(const int* __restrict__ values,
                  const float4* __restrict__ table,
                  float4* __restrict__ out)
{
    const unsigned lane   = threadIdx.x & 31u;
    const unsigned warpId = blockIdx.x * 8u + (threadIdx.x >> 5);
    const unsigned row0   = warpId * ROWS_PER_WARP;
    if (row0 >= N_ROWS) return;

    // 32-bit const division: f = row0 / 81920 (group never crosses feature edge;
    // 81920 % 8 == 0)
    const unsigned f     = row0 / BL;            // umulhi+shift, cheap
    const unsigned i0    = row0 - f * BL;
    const unsigned src_f = f ^ 4u;               // feature-block permutation

    const int* __restrict__ vptr = values + (size_t)src_f * BL + i0;

    // Phase 1: compute all gather addresses (ids are consecutive -> broadcast loads)
    const float4* src[ROWS_PER_WARP];
    #pragma unroll
    for (int k = 0; k < ROWS_PER_WARP; k++) {
        unsigned slot = (unsigned)__ldg(vptr + k) % VOCAB;
        src[k] = table + (size_t)slot * DIM_V4 + lane;
    }

    // Phase 2: issue all gathers back-to-back (MLP=8 per warp, 4KB in flight)
    float4 r[ROWS_PER_WARP];
    #pragma unroll
    for (int k = 0; k < ROWS_PER_WARP; k++)
        r[k] = __ldg(src[k]);

    // Phase 3: 4KB contiguous streaming store (evict-first; don't pollute L2)
    float4* __restrict__ dst = out + (size_t)row0 * DIM_V4 + lane;
    #pragma unroll
    for (int k = 0; k < ROWS_PER_WARP; k++)
        __stcs(dst + k * DIM_V4, r[k]);
}

extern "C" void kernel_launch(void* const* d_in, const int* in_sizes, int n_in,
                              void* d_out, int out_size)
{
    const int*    values = (const int*)d_in[0];
    const float4* table  = (const float4*)d_in[1];
    float4*       out    = (float4*)d_out;

    // 8 warps/block * 8 rows/warp = 64 rows per block; exact cover
    const int blocks = N_ROWS / (8 * ROWS_PER_WARP);   // 10240
    emb_gather_kernel<<<blocks, 256>>>(values, table, out);
}

// round 5
// speedup vs baseline: 1.6542x; 1.0129x over previous
#include <cuda_runtime.h>
#include <cstdint>

// Problem constants (from reference)
#define F_FEATS   8
#define BL        81920u             // 4096*20 ids per feature
#define VOCAB     1000000u
#define DIM_V4    32                 // 128 floats = 32 float4 per row
#define N_ROWS    655360u            // F_FEATS * BL output rows
#define ROWS_PER_WARP 8

// Each warp handles 8 consecutive output rows:
//   - 8 uniform id loads (two L1 sectors)
//   - slots kept as u32 (not pointers) to cut register pressure -> higher occ
//   - 8 back-to-back gather LDG.128 (MLP=8, 4KB in flight per warp)
//   - 8 contiguous streaming STG.128 (__stcs: evict-first, keep L2 for table)
// Output feature f sources input feature f^4 (split_sizes=(4,4), order=(1,0)).
__global__ void __launch_bounds__(256)
emb_gather_kernel(const int* __restrict__ values,
                  const float4* __restrict__ table,
                  float4* __restrict__ out)
{
    const unsigned lane   = threadIdx.x & 31u;
    const unsigned warpId = blockIdx.x * 8u + (threadIdx.x >> 5);
    const unsigned row0   = warpId * ROWS_PER_WARP;
    if (row0 >= N_ROWS) return;

    // 32-bit const division: f = row0 / 81920 (group never crosses a feature
    // edge; 81920 % 8 == 0)
    const unsigned f     = row0 / BL;            // umulhi+shift, cheap
    const unsigned i0    = row0 - f * BL;
    const unsigned src_f = f ^ 4u;               // feature-block permutation

    const int* __restrict__ vptr = values + (size_t)src_f * BL + i0;

    // Phase 1: fetch all 8 slots (consecutive ids -> broadcast loads).
    unsigned slot[ROWS_PER_WARP];
    #pragma unroll
    for (int k = 0; k < ROWS_PER_WARP; k++)
        slot[k] = (unsigned)__ldg(vptr + k) % VOCAB;

    // Phase 2: issue all gathers back-to-back. Address = base + slot*32
    // (single IMAD.WIDE per load; slots stay in 32-bit regs).
    const float4* __restrict__ base = table + lane;
    float4 r[ROWS_PER_WARP];
    #pragma unroll
    for (int k = 0; k < ROWS_PER_WARP; k++)
        r[k] = __ldg(base + (size_t)slot[k] * DIM_V4);

    // Phase 3: 4KB contiguous streaming store (evict-first; don't pollute L2)
    float4* __restrict__ dst = out + (size_t)row0 * DIM_V4 + lane;
    #pragma unroll
    for (int k = 0; k < ROWS_PER_WARP; k++)
        __stcs(dst + k * DIM_V4, r[k]);
}

extern "C" void kernel_launch(void* const* d_in, const int* in_sizes, int n_in,
                              void* d_out, int out_size)
{
    const int*    values = (const int*)d_in[0];
    const float4* table  = (const float4*)d_in[1];
    float4*       out    = (float4*)d_out;

    // 8 warps/block * 8 rows/warp = 64 rows per block; exact cover
    const int blocks = N_ROWS / (8 * ROWS_PER_WARP);   // 10240
    emb_gather_kernel<<<blocks, 256>>>(values, table, out);
}